// round 9
// baseline (speedup 1.0000x reference)
#include <cuda_runtime.h>
#include <cstdint>

#define HH 96
#define WW 96
#define NPIX (HH*WW)

// ---------------- scratch (static device globals; no allocation) ----------------
__device__ float g_x[4*64*NPIX];      // staged x for the 4 (dir,batch) lanes
__device__ float g_h[4*64*NPIX];      // hidden state
__device__ float g_c[4*64*NPIX];      // cell state
__device__ float g_comb[4*64*NPIX];   // fuse conv output
__device__ float g_om[4*216*NPIX];    // offset/mask conv output
__device__ float g_samp[4*576*NPIX];  // DCN sampled im2col matrix [n][cin*9+kk][pix]
__device__ float g_fused[4*128*NPIX]; // DCN output (relu)
__device__ float g_cc[4*256*NPIX];    // gate conv output
__device__ float g_fwd[10*64*NPIX];   // fwd hidden over time  [t*2+b]
__device__ float g_bwd[10*64*NPIX];   // bwd hidden over time  [t*2+b]

__device__ __forceinline__ float sigf(float x){ return 1.f / (1.f + __expf(-x)); }

__device__ __forceinline__ uint32_t s2u(const void* p){
    uint32_t a;
    asm("{ .reg .u64 t; cvta.to.shared.u64 t, %1; cvt.u32.u64 %0, t; }" : "=r"(a) : "l"(p));
    return a;
}
__device__ __forceinline__ uint32_t f2tf32(float f){
    uint32_t r;
    asm("cvt.rna.tf32.f32 %0, %1;" : "=r"(r) : "f"(f));
    return r;
}
__device__ __forceinline__ void ldsm4(uint32_t r[4], uint32_t addr){
    asm volatile("ldmatrix.sync.aligned.m8n8.x4.shared.b16 {%0,%1,%2,%3}, [%4];"
        : "=r"(r[0]), "=r"(r[1]), "=r"(r[2]), "=r"(r[3]) : "r"(addr));
}
__device__ __forceinline__ void mma8(float c[4], const uint32_t a[4], uint32_t b0, uint32_t b1){
    asm volatile(
        "mma.sync.aligned.m16n8k8.row.col.f32.tf32.tf32.f32 "
        "{%0,%1,%2,%3}, {%4,%5,%6,%7}, {%8,%9}, {%0,%1,%2,%3};"
        : "+f"(c[0]), "+f"(c[1]), "+f"(c[2]), "+f"(c[3])
        : "r"(a[0]), "r"(a[1]), "r"(a[2]), "r"(a[3]), "r"(b0), "r"(b1));
}

// SMEM (dynamic, 64KB): A bufs at b*16384, B bufs at 32768 + b*16384 (bytes)
static constexpr int SMEM_GEMM_TOTAL = 65536;

// ================= tf32 mma.sync implicit-GEMM =================
// D[n][co][pix] = sum_k W[co][k] * Im[pix][k]  (+bias, opt relu)
// MODE 0: Im = im2col of conv3x3 over concat(in0[cin0], in1[...]); k = cin*9 + ky*3 + kx
// MODE 1: Im[pix][k] = in0[n][k][pix]
// OUTBT:  n = t*2+b -> out[(b*5+t)][co][pix]
template<int MODE, int ACT, int OUTBT>
__global__ __launch_bounds__(256, 1) void tgemm(
    const float* __restrict__ in0, long s0, int cin0,
    const float* __restrict__ in1, long s1,
    const float* __restrict__ wgt, const float* __restrict__ bias,
    float* __restrict__ out, int Cout, int K)
{
    extern __shared__ char dsm[];
    const uint32_t sb = s2u(dsm);
    const int tid = threadIdx.x;
    const int wid = tid >> 5;
    const int lid = tid & 31;
    const int n   = blockIdx.z;
    const int p0  = blockIdx.x * 128;
    const int co0 = blockIdx.y * 128;

    // ---- staging role: tid<128 stages B row (pixel), tid>=128 stages A row (cout)
    const bool isB = (tid < 128);
    const int  srow = isB ? tid : (tid - 128);
    const int  spg = p0 + srow;
    const int  spy = spg / WW;
    const int  spx = spg - spy * WW;
    const float* base0 = in0 + (long)n * s0;
    const float* base1 = (MODE == 0 && in1) ? (in1 + (long)n * s1) : (const float*)0;
    const int  sco = co0 + srow;
    const bool wok = (sco < Cout);
    const float* wrow = wgt + (long)sco * K;
    const uint32_t stsBase = sb + (isB ? 32768u : 0u) + (uint32_t)srow * 128u;
    const int  sr7 = srow & 7;

    uint32_t sv[32];

    auto ldg_chunk = [&](int kk0) {
        if (isB) {
            if (MODE == 0) {
#pragma unroll
                for (int j = 0; j < 32; j++) {
                    int k   = kk0 + j;
                    int cin = k / 9;
                    int rr  = k - cin * 9;
                    int ky  = rr / 3;
                    int kx  = rr - ky * 3;
                    int iy  = spy + ky - 1;
                    int ix  = spx + kx - 1;
                    float v = 0.f;
                    if (iy >= 0 && iy < HH && ix >= 0 && ix < WW) {
                        const float* srcp = (cin < cin0) ? (base0 + (long)cin * NPIX)
                                                         : (base1 + (long)(cin - cin0) * NPIX);
                        v = __ldg(srcp + iy * WW + ix);
                    }
                    sv[j] = f2tf32(v);
                }
            } else {
#pragma unroll
                for (int j = 0; j < 32; j++)
                    sv[j] = f2tf32(__ldg(base0 + (long)(kk0 + j) * NPIX + spg));
            }
        } else {
            if (wok) {
#pragma unroll
                for (int j = 0; j < 32; j += 4) {
                    float4 w4 = *(const float4*)(wrow + kk0 + j);
                    sv[j]   = f2tf32(w4.x);
                    sv[j+1] = f2tf32(w4.y);
                    sv[j+2] = f2tf32(w4.z);
                    sv[j+3] = f2tf32(w4.w);
                }
            } else {
#pragma unroll
                for (int j = 0; j < 32; j++) sv[j] = 0u;
            }
        }
    };
    auto sts_chunk = [&](int b) {
        uint32_t base = stsBase + (uint32_t)b * 16384u;
#pragma unroll
        for (int c = 0; c < 8; c++) {
            uint32_t addr = base + (uint32_t)((c ^ sr7) << 4);
            asm volatile("st.shared.v4.b32 [%0], {%1, %2, %3, %4};"
                :: "r"(addr), "r"(sv[4*c]), "r"(sv[4*c+1]), "r"(sv[4*c+2]), "r"(sv[4*c+3])
                : "memory");
        }
    };

    // ---- compute-side per-lane ldmatrix address constants
    const int lr = lid & 7;           // row within 8
    const int lm = lid >> 3;          // matrix id 0..3
    const int wco = (wid >> 1) * 32;  // warp cout base within tile
    const int wpx = (wid & 1) * 64;   // warp pixel base within tile
    // A: matrices (0,1)=rows(+0,+8) at col16+0 ; (2,3)=rows(+0,+8) at col16+1
    const int c01A = lm >> 1;
    int rA[2], r7A[2]; uint32_t offA[2];
#pragma unroll
    for (int m = 0; m < 2; m++) {
        rA[m]  = wco + m * 16 + (lm & 1) * 8 + lr;
        r7A[m] = rA[m] & 7;
        offA[m] = (uint32_t)rA[m] * 128u;
    }
    // B: matrices (0,1)=rows+0 at col16 (+0,+1) ; (2,3)=rows+8 at col16 (+0,+1)
    const int c01B = lm & 1;
    int r7B[4]; uint32_t offB[4];
#pragma unroll
    for (int j = 0; j < 4; j++) {
        int rb = wpx + 16 * j + (lm >> 1) * 8 + lr;
        r7B[j] = rb & 7;
        offB[j] = (uint32_t)rb * 128u;
    }

    float acc[2][8][4];
#pragma unroll
    for (int m = 0; m < 2; m++)
#pragma unroll
        for (int j = 0; j < 8; j++)
#pragma unroll
            for (int v = 0; v < 4; v++) acc[m][j][v] = 0.f;

    auto compute_chunk = [&](int b) {
        const uint32_t abase = sb + (uint32_t)b * 16384u;
        const uint32_t bbase = sb + 32768u + (uint32_t)b * 16384u;
#pragma unroll
        for (int s = 0; s < 4; s++) {
            uint32_t Af[2][4];
#pragma unroll
            for (int m = 0; m < 2; m++)
                ldsm4(Af[m], abase + offA[m] + (uint32_t)(((2*s + c01A) ^ r7A[m]) << 4));
            uint32_t Bf[4][4];
#pragma unroll
            for (int j = 0; j < 4; j++)
                ldsm4(Bf[j], bbase + offB[j] + (uint32_t)(((2*s + c01B) ^ r7B[j]) << 4));
#pragma unroll
            for (int m = 0; m < 2; m++)
#pragma unroll
                for (int j = 0; j < 4; j++) {
                    mma8(acc[m][2*j],     Af[m], Bf[j][0], Bf[j][1]);
                    mma8(acc[m][2*j + 1], Af[m], Bf[j][2], Bf[j][3]);
                }
        }
    };

    // ---- pipeline: double-buffered chunks of K=32
    const int nch = K / 32;
    ldg_chunk(0);
    sts_chunk(0);
    __syncthreads();
    for (int i = 0; i < nch; i++) {
        if (i + 1 < nch) ldg_chunk((i + 1) * 32);   // LDG flies under compute
        compute_chunk(i & 1);
        __syncthreads();
        if (i + 1 < nch) {
            sts_chunk((i + 1) & 1);
            __syncthreads();
        }
    }

    // ---- epilogue: registers -> GMEM
    const int g  = lid >> 2;
    const int tg = lid & 3;
#pragma unroll
    for (int m = 0; m < 2; m++) {
        int cobase = co0 + wco + 16 * m + g;
#pragma unroll
        for (int half = 0; half < 2; half++) {
            int co = cobase + 8 * half;
            if (co >= Cout) continue;
            float bsv = bias[co];
            long ob;
            if (OUTBT) {
                int bb = n & 1, tt = n >> 1;
                ob = ((long)(bb * 5 + tt) * Cout + co) * NPIX;
            } else {
                ob = ((long)n * Cout + co) * NPIX;
            }
            ob += p0 + wpx + 2 * tg;
#pragma unroll
            for (int j = 0; j < 8; j++) {
                float2 o;
                o.x = acc[m][j][2*half]     + bsv;
                o.y = acc[m][j][2*half + 1] + bsv;
                if (ACT) { o.x = fmaxf(o.x, 0.f); o.y = fmaxf(o.y, 0.f); }
                *(float2*)(out + ob + 8 * j) = o;
            }
        }
    }
}

// ---------------- stage x slices for the 4 lanes ----------------
__global__ void stage_x(const float* __restrict__ inp, int t)
{
    int id = blockIdx.x * blockDim.x + threadIdx.x;
    int p  = id % NPIX;
    int r  = id / NPIX;
    int ch = r % 64;
    int n  = r / 64;
    int b  = n & 1;
    int ts = (n < 2) ? t : (4 - t);
    g_x[id] = inp[(((long)b * 5 + ts) * 64 + ch) * NPIX + p];
}

// ---------------- DCN bilinear sampler -> sampled im2col matrix ----------------
__global__ void dcn_sample(const float* __restrict__ om, const float* __restrict__ hbuf,
                           float* __restrict__ samp)
{
    int id = blockIdx.x * blockDim.x + threadIdx.x;
    int p  = id % NPIX;
    int r  = id / NPIX;
    int kk = r % 9;  r /= 9;
    int g  = r % 8;
    int n  = r / 8;

    const float* omb = om + (long)n * 216 * NPIX;
    float offy = omb[((g * 9 + kk) * 2 + 0) * NPIX + p];
    float offx = omb[((g * 9 + kk) * 2 + 1) * NPIX + p];
    float m    = sigf(omb[(144 + g * 9 + kk) * NPIX + p]);

    int y  = p / WW;
    int x  = p - y * WW;
    int ky = kk / 3;
    int kx = kk - ky * 3;
    float py = (float)(y + ky - 1) + offy;
    float px = (float)(x + kx - 1) + offx;
    float fy = floorf(py), fx = floorf(px);
    float wy = py - fy,    wx = px - fx;
    int y0 = (int)fy, x0 = (int)fx;
    int y1 = y0 + 1,  x1 = x0 + 1;

    bool vy0 = (y0 >= 0) & (y0 < HH);
    bool vy1 = (y1 >= 0) & (y1 < HH);
    bool vx0 = (x0 >= 0) & (x0 < WW);
    bool vx1 = (x1 >= 0) & (x1 < WW);
    float w00 = (1.f - wy) * (1.f - wx) * (float)(vy0 && vx0);
    float w01 = (1.f - wy) * wx         * (float)(vy0 && vx1);
    float w10 = wy * (1.f - wx)         * (float)(vy1 && vx0);
    float w11 = wy * wx                 * (float)(vy1 && vx1);

    int cy0 = min(max(y0, 0), HH - 1), cy1 = min(max(y1, 0), HH - 1);
    int cx0 = min(max(x0, 0), WW - 1), cx1 = min(max(x1, 0), WW - 1);
    int i00 = cy0 * WW + cx0, i01 = cy0 * WW + cx1;
    int i10 = cy1 * WW + cx0, i11 = cy1 * WW + cx1;

    const float* hb = hbuf + ((long)n * 64 + g * 8) * NPIX;
    float* sbp = samp + (long)n * 576 * NPIX + (long)(g * 8) * 9 * NPIX + (long)kk * NPIX + p;
#pragma unroll
    for (int cg = 0; cg < 8; cg++) {
        const float* f = hb + (long)cg * NPIX;
        float v = w00 * f[i00] + w01 * f[i01] + w10 * f[i10] + w11 * f[i11];
        sbp[(long)cg * 9 * NPIX] = v * m;
    }
}

// ---------------- LSTM pointwise update ----------------
__global__ void lstm_k(const float* __restrict__ cc, float* __restrict__ hbuf,
                       float* __restrict__ cbuf, float* __restrict__ fwdb,
                       float* __restrict__ bwdb, int t)
{
    int id = blockIdx.x * blockDim.x + threadIdx.x;
    int p  = id % NPIX;
    int r  = id / NPIX;
    int ch = r % 64;
    int n  = r / 64;

    const float* c4 = cc + (long)n * 256 * NPIX;
    float ci = c4[(      ch) * NPIX + p];
    float cf = c4[( 64 + ch) * NPIX + p];
    float co = c4[(128 + ch) * NPIX + p];
    float cg = c4[(192 + ch) * NPIX + p];

    long hi = ((long)n * 64 + ch) * NPIX + p;
    float c  = cbuf[hi];
    float c2 = sigf(cf) * c + sigf(ci) * tanhf(cg);
    float h2 = sigf(co) * tanhf(c2);
    cbuf[hi] = c2;
    hbuf[hi] = h2;

    long o = (long)ch * NPIX + p;
    if (n < 2) fwdb[(long)(t * 2 + n) * 64 * NPIX + o] = h2;
    else       bwdb[(long)((4 - t) * 2 + (n - 2)) * 64 * NPIX + o] = h2;
}

// ---------------- host orchestration (graph-capturable) ----------------
extern "C" void kernel_launch(void* const* d_in, const int* in_sizes, int n_in,
                              void* d_out, int out_size)
{
    (void)in_sizes; (void)n_in; (void)out_size;
    const float* inp    = (const float*)d_in[0];
    const float* fuse_w = (const float*)d_in[1];
    const float* fuse_b = (const float*)d_in[2];
    const float* om_w   = (const float*)d_in[3];
    const float* om_b   = (const float*)d_in[4];
    const float* dcn_w  = (const float*)d_in[5];
    const float* dcn_b  = (const float*)d_in[6];
    const float* conv_w = (const float*)d_in[7];
    const float* conv_b = (const float*)d_in[8];
    const float* cat_w  = (const float*)d_in[9];
    const float* cat_b  = (const float*)d_in[10];

    float *xb, *hb, *cb, *comb, *omb, *sbuf, *fub, *ccb, *fwdb, *bwdb;
    cudaGetSymbolAddress((void**)&xb,   g_x);
    cudaGetSymbolAddress((void**)&hb,   g_h);
    cudaGetSymbolAddress((void**)&cb,   g_c);
    cudaGetSymbolAddress((void**)&comb, g_comb);
    cudaGetSymbolAddress((void**)&omb,  g_om);
    cudaGetSymbolAddress((void**)&sbuf, g_samp);
    cudaGetSymbolAddress((void**)&fub,  g_fused);
    cudaGetSymbolAddress((void**)&ccb,  g_cc);
    cudaGetSymbolAddress((void**)&fwdb, g_fwd);
    cudaGetSymbolAddress((void**)&bwdb, g_bwd);

    cudaFuncSetAttribute(tgemm<0,0,0>, cudaFuncAttributeMaxDynamicSharedMemorySize, SMEM_GEMM_TOTAL);
    cudaFuncSetAttribute(tgemm<1,1,0>, cudaFuncAttributeMaxDynamicSharedMemorySize, SMEM_GEMM_TOTAL);
    cudaFuncSetAttribute(tgemm<0,0,1>, cudaFuncAttributeMaxDynamicSharedMemorySize, SMEM_GEMM_TOTAL);

    cudaMemsetAsync(hb, 0, sizeof(float) * 4 * 64 * NPIX);
    cudaMemsetAsync(cb, 0, sizeof(float) * 4 * 64 * NPIX);

    for (int t = 0; t < 5; t++) {
        stage_x<<<(4*64*NPIX)/256, 256>>>(inp, t);
        // combined = conv3x3(concat(x, h)) : Cout=64, K=1152
        tgemm<0,0,0><<<dim3(72, 1, 4), 256, SMEM_GEMM_TOTAL>>>(
            xb, 64L*NPIX, 64, hb, 64L*NPIX, fuse_w, fuse_b, comb, 64, 1152);
        // om = conv3x3(combined) : Cout=216, K=576
        tgemm<0,0,0><<<dim3(72, 2, 4), 256, SMEM_GEMM_TOTAL>>>(
            comb, 64L*NPIX, 64, (const float*)0, 0, om_w, om_b, omb, 216, 576);
        // DCN sampling -> sampled matrix [576][NPIX]
        dcn_sample<<<(4*8*9*NPIX)/256, 256>>>(omb, hb, sbuf);
        // fused = relu(W_dcn @ sampled + b) : Cout=128, K=576 (dense)
        tgemm<1,1,0><<<dim3(72, 1, 4), 256, SMEM_GEMM_TOTAL>>>(
            sbuf, 576L*NPIX, 0, (const float*)0, 0, dcn_w, dcn_b, fub, 128, 576);
        // cc = conv3x3(fused) : Cout=256, K=1152
        tgemm<0,0,0><<<dim3(72, 2, 4), 256, SMEM_GEMM_TOTAL>>>(
            fub, 128L*NPIX, 128, (const float*)0, 0, conv_w, conv_b, ccb, 256, 1152);
        // LSTM gates + state update
        lstm_k<<<(4*64*NPIX)/256, 256>>>(ccb, hb, cb, fwdb, bwdb, t);
    }

    // out[b][t] = conv3x3(concat(fwd[t], bwd[t])) over all 10 (t,b) pairs
    tgemm<0,0,1><<<dim3(72, 1, 10), 256, SMEM_GEMM_TOTAL>>>(
        fwdb, 64L*NPIX, 64, bwdb, 64L*NPIX, cat_w, cat_b, (float*)d_out, 64, 1152);
}

// round 10
// speedup vs baseline: 2.0428x; 2.0428x over previous
#include <cuda_runtime.h>
#include <cuda_fp16.h>
#include <cstdint>

#define HH 96
#define WW 96
#define NPIX (HH*WW)

// ---------------- scratch (static device globals; no allocation) ----------------
__device__ float g_x[4*64*NPIX];      // staged x for the 4 (dir,batch) lanes
__device__ float g_h[4*64*NPIX];      // hidden state
__device__ float g_c[4*64*NPIX];      // cell state
__device__ float g_comb[4*64*NPIX];   // fuse conv output
__device__ float g_om[4*216*NPIX];    // offset/mask conv output
__device__ float g_samp[4*576*NPIX];  // DCN sampled im2col matrix [n][cin*9+kk][pix]
__device__ float g_fused[4*128*NPIX]; // DCN output (relu)
__device__ float g_cc[4*256*NPIX];    // gate conv output
__device__ float g_fwd[10*64*NPIX];   // fwd hidden over time  [t*2+b]
__device__ float g_bwd[10*64*NPIX];   // bwd hidden over time  [t*2+b]

__device__ __forceinline__ float sigf(float x){ return 1.f / (1.f + __expf(-x)); }

__device__ __forceinline__ uint32_t s2u(const void* p){
    uint32_t a;
    asm("{ .reg .u64 t; cvta.to.shared.u64 t, %1; cvt.u32.u64 %0, t; }" : "=r"(a) : "l"(p));
    return a;
}
__device__ __forceinline__ uint32_t f2h2(float a, float b){
    __half2 h = __floats2half2_rn(a, b);   // low = a (even k), high = b (odd k)
    return *reinterpret_cast<uint32_t*>(&h);
}
__device__ __forceinline__ void ldsm4(uint32_t r[4], uint32_t addr){
    asm volatile("ldmatrix.sync.aligned.m8n8.x4.shared.b16 {%0,%1,%2,%3}, [%4];"
        : "=r"(r[0]), "=r"(r[1]), "=r"(r[2]), "=r"(r[3]) : "r"(addr));
}
// m16n8k16 f16 MMA, f32 accumulate
__device__ __forceinline__ void mma16(float c[4], const uint32_t a[4], uint32_t b0, uint32_t b1){
    asm volatile(
        "mma.sync.aligned.m16n8k16.row.col.f32.f16.f16.f32 "
        "{%0,%1,%2,%3}, {%4,%5,%6,%7}, {%8,%9}, {%0,%1,%2,%3};"
        : "+f"(c[0]), "+f"(c[1]), "+f"(c[2]), "+f"(c[3])
        : "r"(a[0]), "r"(a[1]), "r"(a[2]), "r"(a[3]), "r"(b0), "r"(b1));
}

// SMEM (dynamic, 64KB): A bufs at b*16384, B bufs at 32768 + b*16384
// Each buf: 128 rows x 128B (64 halves = one K-chunk of 64)
static constexpr int SMEM_GEMM_TOTAL = 65536;

// ================= f16 mma.sync implicit-GEMM =================
// D[n][co][pix] = sum_k W[co][k] * Im[pix][k]  (+bias, opt relu)
// MODE 0: Im = im2col of conv3x3 over concat(in0[cin0], in1[...]); k = cin*9 + ky*3 + kx
// MODE 1: Im[pix][k] = in0[n][k][pix]
// OUTBT:  n = t*2+b -> out[(b*5+t)][co][pix]
template<int MODE, int ACT, int OUTBT>
__global__ __launch_bounds__(256, 1) void tgemm(
    const float* __restrict__ in0, long s0, int cin0,
    const float* __restrict__ in1, long s1,
    const float* __restrict__ wgt, const float* __restrict__ bias,
    float* __restrict__ out, int Cout, int K)
{
    extern __shared__ char dsm[];
    const uint32_t sb = s2u(dsm);
    const int tid = threadIdx.x;
    const int wid = tid >> 5;
    const int lid = tid & 31;
    const int n   = blockIdx.z;
    const int p0  = blockIdx.x * 128;
    const int co0 = blockIdx.y * 128;

    // ---- staging role: tid<128 stages B row (pixel), tid>=128 stages A row (cout)
    const bool isB = (tid < 128);
    const int  srow = isB ? tid : (tid - 128);
    const int  spg = p0 + srow;
    const int  spy = spg / WW;
    const int  spx = spg - spy * WW;
    const float* base0 = in0 + (long)n * s0;
    const float* base1 = (MODE == 0 && in1) ? (in1 + (long)n * s1) : (const float*)0;
    const int  sco = co0 + srow;
    const bool wok = (sco < Cout);
    const float* wrow = wgt + (long)sco * K;
    const uint32_t stsBase = sb + (isB ? 32768u : 0u) + (uint32_t)srow * 128u;
    const int  sr7 = srow & 7;

    float    lv[32];   // raw staged floats (one 32-k half-chunk)
    uint32_t sv[16];   // packed f16x2

    // load one half-chunk (32 k's) as raw floats; NO conversion here so the
    // LDGs can fly under the following compute_half
    auto ldg_half = [&](int kk0) {
        if (isB) {
            if (MODE == 0) {
#pragma unroll
                for (int j = 0; j < 32; j++) {
                    int k   = kk0 + j;
                    int cin = k / 9;
                    int rr  = k - cin * 9;
                    int ky  = rr / 3;
                    int kx  = rr - ky * 3;
                    int iy  = spy + ky - 1;
                    int ix  = spx + kx - 1;
                    float v = 0.f;
                    if (iy >= 0 && iy < HH && ix >= 0 && ix < WW) {
                        const float* srcp = (cin < cin0) ? (base0 + (long)cin * NPIX)
                                                         : (base1 + (long)(cin - cin0) * NPIX);
                        v = __ldg(srcp + iy * WW + ix);
                    }
                    lv[j] = v;
                }
            } else {
#pragma unroll
                for (int j = 0; j < 32; j++)
                    lv[j] = __ldg(base0 + (long)(kk0 + j) * NPIX + spg);
            }
        } else {
            if (wok) {
#pragma unroll
                for (int j = 0; j < 32; j += 4) {
                    float4 w4 = *(const float4*)(wrow + kk0 + j);
                    lv[j] = w4.x; lv[j+1] = w4.y; lv[j+2] = w4.z; lv[j+3] = w4.w;
                }
            } else {
#pragma unroll
                for (int j = 0; j < 32; j++) lv[j] = 0.f;
            }
        }
    };
    // convert + store one half-chunk: groups 4h..4h+3 of the 8 16B groups in the row
    auto cvt_sts_half = [&](int b, int h) {
#pragma unroll
        for (int j2 = 0; j2 < 16; j2++) sv[j2] = f2h2(lv[2*j2], lv[2*j2 + 1]);
        uint32_t base = stsBase + (uint32_t)b * 16384u;
#pragma unroll
        for (int c = 0; c < 4; c++) {
            int cg = 4*h + c;                       // logical 16B group (k = 8cg..8cg+7)
            uint32_t addr = base + (uint32_t)((cg ^ sr7) << 4);
            asm volatile("st.shared.v4.b32 [%0], {%1, %2, %3, %4};"
                :: "r"(addr), "r"(sv[4*c]), "r"(sv[4*c+1]), "r"(sv[4*c+2]), "r"(sv[4*c+3])
                : "memory");
        }
    };

    // ---- compute-side ldmatrix geometry
    const int lr = lid & 7;
    const int q  = lid >> 3;          // which 8x8 matrix this lane addresses
    const int wco = (wid >> 1) * 32;  // warp cout base (2 m16 tiles)
    const int wpx = (wid & 1) * 64;   // warp pixel base (8 n8 tiles)
    // A x4 = [(r0,k0),(r8,k0),(r0,k8),(r8,k8)] : row += (q&1)*8, ksel = q>>1
    uint32_t offA[2]; int r7A[2]; const int kselA = q >> 1;
#pragma unroll
    for (int m = 0; m < 2; m++) {
        int r = wco + 16*m + (q & 1)*8 + lr;
        offA[m] = (uint32_t)r * 128u;  r7A[m] = r & 7;
    }
    // B x4 = [(n0,k0),(n0,k8),(n8,k0),(n8,k8)] : row += (q>>1)*8, ksel = q&1
    uint32_t offB[4]; int r7B[4]; const int kselB = q & 1;
#pragma unroll
    for (int j = 0; j < 4; j++) {
        int r = wpx + 16*j + (q >> 1)*8 + lr;
        offB[j] = (uint32_t)r * 128u;  r7B[j] = r & 7;
    }

    float acc[2][8][4];
#pragma unroll
    for (int m = 0; m < 2; m++)
#pragma unroll
        for (int j = 0; j < 8; j++)
#pragma unroll
            for (int v = 0; v < 4; v++) acc[m][j][v] = 0.f;

    // two k16 steps (s = s0, s0+1) on buffer b
    auto compute_half = [&](int b, int s0q) {
        const uint32_t abase = sb + (uint32_t)b * 16384u;
        const uint32_t bbase = sb + 32768u + (uint32_t)b * 16384u;
#pragma unroll
        for (int ss = 0; ss < 2; ss++) {
            const int s = s0q + ss;
            uint32_t Af[2][4];
#pragma unroll
            for (int m = 0; m < 2; m++)
                ldsm4(Af[m], abase + offA[m] + (uint32_t)(((2*s + kselA) ^ r7A[m]) << 4));
#pragma unroll
            for (int j = 0; j < 4; j++) {
                uint32_t Bf[4];
                ldsm4(Bf, bbase + offB[j] + (uint32_t)(((2*s + kselB) ^ r7B[j]) << 4));
#pragma unroll
                for (int m = 0; m < 2; m++) {
                    mma16(acc[m][2*j],     Af[m], Bf[0], Bf[1]);
                    mma16(acc[m][2*j + 1], Af[m], Bf[2], Bf[3]);
                }
            }
        }
    };

    // ---- pipeline: K-chunks of 64, double-buffered, ONE sync per chunk,
    //      LDGs always issued before the compute half they hide under
    const int nch = K / 64;
    ldg_half(0);       cvt_sts_half(0, 0);
    ldg_half(32);      cvt_sts_half(0, 1);
    __syncthreads();
    for (int i = 0; i < nch; i++) {
        const int b = i & 1;
        const bool more = (i + 1 < nch);
        if (more) ldg_half((i + 1) * 64);
        compute_half(b, 0);
        if (more) { cvt_sts_half(b ^ 1, 0); ldg_half((i + 1) * 64 + 32); }
        compute_half(b, 2);
        if (more) cvt_sts_half(b ^ 1, 1);
        __syncthreads();
    }

    // ---- epilogue: registers -> GMEM (same fragment mapping as R9)
    const int g  = lid >> 2;
    const int tg = lid & 3;
#pragma unroll
    for (int m = 0; m < 2; m++) {
        int cobase = co0 + wco + 16 * m + g;
#pragma unroll
        for (int half = 0; half < 2; half++) {
            int co = cobase + 8 * half;
            if (co >= Cout) continue;
            float bsv = bias[co];
            long ob;
            if (OUTBT) {
                int bb = n & 1, tt = n >> 1;
                ob = ((long)(bb * 5 + tt) * Cout + co) * NPIX;
            } else {
                ob = ((long)n * Cout + co) * NPIX;
            }
            ob += p0 + wpx + 2 * tg;
#pragma unroll
            for (int j = 0; j < 8; j++) {
                float2 o;
                o.x = acc[m][j][2*half]     + bsv;
                o.y = acc[m][j][2*half + 1] + bsv;
                if (ACT) { o.x = fmaxf(o.x, 0.f); o.y = fmaxf(o.y, 0.f); }
                *(float2*)(out + ob + 8 * j) = o;
            }
        }
    }
}

// ---------------- stage x slices for the 4 lanes ----------------
__global__ void stage_x(const float* __restrict__ inp, int t)
{
    int id = blockIdx.x * blockDim.x + threadIdx.x;
    int p  = id % NPIX;
    int r  = id / NPIX;
    int ch = r % 64;
    int n  = r / 64;
    int b  = n & 1;
    int ts = (n < 2) ? t : (4 - t);
    g_x[id] = inp[(((long)b * 5 + ts) * 64 + ch) * NPIX + p];
}

// ---------------- DCN bilinear sampler -> sampled im2col matrix ----------------
__global__ void dcn_sample(const float* __restrict__ om, const float* __restrict__ hbuf,
                           float* __restrict__ samp)
{
    int id = blockIdx.x * blockDim.x + threadIdx.x;
    int p  = id % NPIX;
    int r  = id / NPIX;
    int kk = r % 9;  r /= 9;
    int g  = r % 8;
    int n  = r / 8;

    const float* omb = om + (long)n * 216 * NPIX;
    float offy = omb[((g * 9 + kk) * 2 + 0) * NPIX + p];
    float offx = omb[((g * 9 + kk) * 2 + 1) * NPIX + p];
    float m    = sigf(omb[(144 + g * 9 + kk) * NPIX + p]);

    int y  = p / WW;
    int x  = p - y * WW;
    int ky = kk / 3;
    int kx = kk - ky * 3;
    float py = (float)(y + ky - 1) + offy;
    float px = (float)(x + kx - 1) + offx;
    float fy = floorf(py), fx = floorf(px);
    float wy = py - fy,    wx = px - fx;
    int y0 = (int)fy, x0 = (int)fx;
    int y1 = y0 + 1,  x1 = x0 + 1;

    bool vy0 = (y0 >= 0) & (y0 < HH);
    bool vy1 = (y1 >= 0) & (y1 < HH);
    bool vx0 = (x0 >= 0) & (x0 < WW);
    bool vx1 = (x1 >= 0) & (x1 < WW);
    float w00 = (1.f - wy) * (1.f - wx) * (float)(vy0 && vx0);
    float w01 = (1.f - wy) * wx         * (float)(vy0 && vx1);
    float w10 = wy * (1.f - wx)         * (float)(vy1 && vx0);
    float w11 = wy * wx                 * (float)(vy1 && vx1);

    int cy0 = min(max(y0, 0), HH - 1), cy1 = min(max(y1, 0), HH - 1);
    int cx0 = min(max(x0, 0), WW - 1), cx1 = min(max(x1, 0), WW - 1);
    int i00 = cy0 * WW + cx0, i01 = cy0 * WW + cx1;
    int i10 = cy1 * WW + cx0, i11 = cy1 * WW + cx1;

    const float* hb = hbuf + ((long)n * 64 + g * 8) * NPIX;
    float* sbp = samp + (long)n * 576 * NPIX + (long)(g * 8) * 9 * NPIX + (long)kk * NPIX + p;
#pragma unroll
    for (int cg = 0; cg < 8; cg++) {
        const float* f = hb + (long)cg * NPIX;
        float v = w00 * f[i00] + w01 * f[i01] + w10 * f[i10] + w11 * f[i11];
        sbp[(long)cg * 9 * NPIX] = v * m;
    }
}

// ---------------- LSTM pointwise update ----------------
__global__ void lstm_k(const float* __restrict__ cc, float* __restrict__ hbuf,
                       float* __restrict__ cbuf, float* __restrict__ fwdb,
                       float* __restrict__ bwdb, int t)
{
    int id = blockIdx.x * blockDim.x + threadIdx.x;
    int p  = id % NPIX;
    int r  = id / NPIX;
    int ch = r % 64;
    int n  = r / 64;

    const float* c4 = cc + (long)n * 256 * NPIX;
    float ci = c4[(      ch) * NPIX + p];
    float cf = c4[( 64 + ch) * NPIX + p];
    float co = c4[(128 + ch) * NPIX + p];
    float cg = c4[(192 + ch) * NPIX + p];

    long hi = ((long)n * 64 + ch) * NPIX + p;
    float c  = cbuf[hi];
    float c2 = sigf(cf) * c + sigf(ci) * tanhf(cg);
    float h2 = sigf(co) * tanhf(c2);
    cbuf[hi] = c2;
    hbuf[hi] = h2;

    long o = (long)ch * NPIX + p;
    if (n < 2) fwdb[(long)(t * 2 + n) * 64 * NPIX + o] = h2;
    else       bwdb[(long)((4 - t) * 2 + (n - 2)) * 64 * NPIX + o] = h2;
}

// ---------------- host orchestration (graph-capturable) ----------------
extern "C" void kernel_launch(void* const* d_in, const int* in_sizes, int n_in,
                              void* d_out, int out_size)
{
    (void)in_sizes; (void)n_in; (void)out_size;
    const float* inp    = (const float*)d_in[0];
    const float* fuse_w = (const float*)d_in[1];
    const float* fuse_b = (const float*)d_in[2];
    const float* om_w   = (const float*)d_in[3];
    const float* om_b   = (const float*)d_in[4];
    const float* dcn_w  = (const float*)d_in[5];
    const float* dcn_b  = (const float*)d_in[6];
    const float* conv_w = (const float*)d_in[7];
    const float* conv_b = (const float*)d_in[8];
    const float* cat_w  = (const float*)d_in[9];
    const float* cat_b  = (const float*)d_in[10];

    float *xb, *hb, *cb, *comb, *omb, *sbuf, *fub, *ccb, *fwdb, *bwdb;
    cudaGetSymbolAddress((void**)&xb,   g_x);
    cudaGetSymbolAddress((void**)&hb,   g_h);
    cudaGetSymbolAddress((void**)&cb,   g_c);
    cudaGetSymbolAddress((void**)&comb, g_comb);
    cudaGetSymbolAddress((void**)&omb,  g_om);
    cudaGetSymbolAddress((void**)&sbuf, g_samp);
    cudaGetSymbolAddress((void**)&fub,  g_fused);
    cudaGetSymbolAddress((void**)&ccb,  g_cc);
    cudaGetSymbolAddress((void**)&fwdb, g_fwd);
    cudaGetSymbolAddress((void**)&bwdb, g_bwd);

    cudaFuncSetAttribute(tgemm<0,0,0>, cudaFuncAttributeMaxDynamicSharedMemorySize, SMEM_GEMM_TOTAL);
    cudaFuncSetAttribute(tgemm<1,1,0>, cudaFuncAttributeMaxDynamicSharedMemorySize, SMEM_GEMM_TOTAL);
    cudaFuncSetAttribute(tgemm<0,0,1>, cudaFuncAttributeMaxDynamicSharedMemorySize, SMEM_GEMM_TOTAL);

    cudaMemsetAsync(hb, 0, sizeof(float) * 4 * 64 * NPIX);
    cudaMemsetAsync(cb, 0, sizeof(float) * 4 * 64 * NPIX);

    for (int t = 0; t < 5; t++) {
        stage_x<<<(4*64*NPIX)/256, 256>>>(inp, t);
        // combined = conv3x3(concat(x, h)) : Cout=64, K=1152 (18 chunks)
        tgemm<0,0,0><<<dim3(72, 1, 4), 256, SMEM_GEMM_TOTAL>>>(
            xb, 64L*NPIX, 64, hb, 64L*NPIX, fuse_w, fuse_b, comb, 64, 1152);
        // om = conv3x3(combined) : Cout=216, K=576 (9 chunks)
        tgemm<0,0,0><<<dim3(72, 2, 4), 256, SMEM_GEMM_TOTAL>>>(
            comb, 64L*NPIX, 64, (const float*)0, 0, om_w, om_b, omb, 216, 576);
        // DCN sampling -> sampled matrix [576][NPIX]
        dcn_sample<<<(4*8*9*NPIX)/256, 256>>>(omb, hb, sbuf);
        // fused = relu(W_dcn @ sampled + b) : Cout=128, K=576 (dense)
        tgemm<1,1,0><<<dim3(72, 1, 4), 256, SMEM_GEMM_TOTAL>>>(
            sbuf, 576L*NPIX, 0, (const float*)0, 0, dcn_w, dcn_b, fub, 128, 576);
        // cc = conv3x3(fused) : Cout=256, K=1152
        tgemm<0,0,0><<<dim3(72, 2, 4), 256, SMEM_GEMM_TOTAL>>>(
            fub, 128L*NPIX, 128, (const float*)0, 0, conv_w, conv_b, ccb, 256, 1152);
        // LSTM gates + state update
        lstm_k<<<(4*64*NPIX)/256, 256>>>(ccb, hb, cb, fwdb, bwdb, t);
    }

    // out[b][t] = conv3x3(concat(fwd[t], bwd[t])) over all 10 (t,b) pairs
    tgemm<0,0,1><<<dim3(72, 1, 10), 256, SMEM_GEMM_TOTAL>>>(
        fwdb, 64L*NPIX, 64, bwdb, 64L*NPIX, cat_w, cat_b, (float*)d_out, 64, 1152);
}

// round 11
// speedup vs baseline: 3.0287x; 1.4827x over previous
#include <cuda_runtime.h>
#include <cuda_fp16.h>
#include <cstdint>

#define HH 96
#define WW 96
#define NPIX (HH*WW)
#define PADW 100
#define PPIX 9800   // 98 rows x 100 cols, interior (y,x) -> (y+1)*100 + (x+2)

// ---------------- scratch (static device globals; no allocation) ----------------
__device__ __half g_xh[4*128*PPIX];     // ch 0-63: x, ch 64-127: h   (padded fp16)
__device__ float  g_c[4*64*NPIX];       // cell state (f32)
__device__ __half g_comb[4*64*PPIX];    // fuse conv output (padded fp16)
__device__ float  g_om[4*216*NPIX];     // offset/mask conv output (f32)
__device__ __half g_sampt[4*9216*576];  // DCN sampled matrix, [n][pix][k] fp16
__device__ __half g_fused[4*128*PPIX];  // DCN output, relu (padded fp16)
__device__ float  g_cc[4*256*NPIX];     // gate conv output (f32)
__device__ __half g_fb[10*128*PPIX];    // cat input: ch0-63 fwd h, ch64-127 bwd h
__device__ __half g_wh[640512];         // all weights fp16 (conv weights r-major)

// weight offsets in g_wh
#define WF_FUSE 0
#define WF_OM   73728
#define WF_DCN  198144
#define WF_CC   271872
#define WF_CAT  566784

__device__ __forceinline__ float sigf(float x){ return 1.f / (1.f + __expf(-x)); }

__device__ __forceinline__ uint32_t s2u(const void* p){
    uint32_t a;
    asm("{ .reg .u64 t; cvta.to.shared.u64 t, %1; cvt.u32.u64 %0, t; }" : "=r"(a) : "l"(p));
    return a;
}
__device__ __forceinline__ void ldsm4(uint32_t r[4], uint32_t addr){
    asm volatile("ldmatrix.sync.aligned.m8n8.x4.shared.b16 {%0,%1,%2,%3}, [%4];"
        : "=r"(r[0]), "=r"(r[1]), "=r"(r[2]), "=r"(r[3]) : "r"(addr));
}
__device__ __forceinline__ void mma16(float c[4], const uint32_t a[4], uint32_t b0, uint32_t b1){
    asm volatile(
        "mma.sync.aligned.m16n8k16.row.col.f32.f16.f16.f32 "
        "{%0,%1,%2,%3}, {%4,%5,%6,%7}, {%8,%9}, {%0,%1,%2,%3};"
        : "+f"(c[0]), "+f"(c[1]), "+f"(c[2]), "+f"(c[3])
        : "r"(a[0]), "r"(a[1]), "r"(a[2]), "r"(a[3]), "r"(b0), "r"(b1));
}

static constexpr int SMEM_GEMM_TOTAL = 65536;

// ================= f16 HMMA implicit-GEMM =================
// D[n][co][pix] = sum_k W[co][k] * Im[pix][k]  (+bias, opt relu)
// MODE 0: conv3x3 over padded fp16 buffer, k-order r-major: k = r*Cin + cin
//         (weights pre-permuted to match). Cin = 1<<cinlog.
// MODE 1: Im[pix][k] = in0[n][pix][k]  (dense k-contiguous fp16 rows)
// OUTM 0: f32 flat [n][Cout][NPIX] ; 1: fp16 padded [n][co][PPIX] (oLane=ch*PPIX)
// OUTM 2: f32 flat with n=t*2+b -> [(b*5+t)][co][NPIX]
template<int MODE, int ACT, int OUTM>
__global__ __launch_bounds__(256, 2) void tgemm(
    const __half* __restrict__ in0, long s0, int cinlog,
    const __half* __restrict__ wh, const float* __restrict__ bias,
    void* __restrict__ out, long oLane, int Cout, int K)
{
    extern __shared__ char dsm[];
    const uint32_t sb = s2u(dsm);
    const int tid = threadIdx.x;
    const int wid = tid >> 5;
    const int lid = tid & 31;
    const int n   = blockIdx.z;
    const int p0  = blockIdx.x * 128;
    const int co0 = blockIdx.y * 128;

    // ---- staging role: tid<128 stages B row (pixel), tid>=128 stages A row (cout)
    const bool isB = (tid < 128);
    const int  srow = isB ? tid : (tid - 128);
    const int  spg = p0 + srow;
    const int  spy = spg / WW;
    const int  spx = spg - spy * WW;
    const int  sco = co0 + srow;
    const bool wok = (sco < Cout);
    // B mode0: padded lane base incl. pixel ; mode1: dense row
    const unsigned short* laneB =
        (const unsigned short*)(in0 + (long)n * s0) + (long)(spy + 1) * PADW + (spx + 2);
    const uint4* rowB1 = (const uint4*)(in0 + (long)n * s0 + (long)spg * 576);
    const uint4* wrow  = (const uint4*)(wh + (long)sco * K);
    const uint32_t stsRole = sb + (isB ? 32768u : 0u) + (uint32_t)srow * 128u;
    const int  sr7 = srow & 7;

    unsigned hv[16];   // B mode0 raw u16 quarter
    unsigned st[8];    // staged u32 quarter (A / B-vector direct, B-mode0 packed later)

    // load one quarter (16 k's): kk0 = chunk*64 + q*16
    auto ldgQ = [&](int kk0) {
        if (isB) {
            if (MODE == 0) {
                const int r    = kk0 >> cinlog;
                const int cinb = kk0 & ((1 << cinlog) - 1);
                const int dy   = r / 3;
                const int pdv  = (dy - 1) * PADW + (r - dy * 3 - 1);
                const unsigned short* bt = laneB + (long)cinb * PPIX + pdv;
#pragma unroll
                for (int j = 0; j < 16; j++)
                    hv[j] = __ldg(bt + (long)j * PPIX);
            } else {
                const uint4* rp = rowB1 + (kk0 >> 3);
                uint4 q0 = __ldg(rp);
                uint4 q1 = __ldg(rp + 1);
                st[0]=q0.x; st[1]=q0.y; st[2]=q0.z; st[3]=q0.w;
                st[4]=q1.x; st[5]=q1.y; st[6]=q1.z; st[7]=q1.w;
            }
        } else {
            if (wok) {
                const uint4* wp = wrow + (kk0 >> 3);
                uint4 q0 = __ldg(wp);
                uint4 q1 = __ldg(wp + 1);
                st[0]=q0.x; st[1]=q0.y; st[2]=q0.z; st[3]=q0.w;
                st[4]=q1.x; st[5]=q1.y; st[6]=q1.z; st[7]=q1.w;
            } else {
#pragma unroll
                for (int j = 0; j < 8; j++) st[j] = 0u;
            }
        }
    };
    // store quarter q of buffer b (16 k -> groups cg=2q, 2q+1)
    auto stsQ = [&](int b, int q) {
        if (isB && MODE == 0) {
#pragma unroll
            for (int j = 0; j < 8; j++)
                st[j] = hv[2*j] | (hv[2*j + 1] << 16);
        }
        uint32_t base = stsRole + (uint32_t)b * 16384u;
#pragma unroll
        for (int c = 0; c < 2; c++) {
            int cg = 2*q + c;
            uint32_t addr = base + (uint32_t)((cg ^ sr7) << 4);
            asm volatile("st.shared.v4.b32 [%0], {%1, %2, %3, %4};"
                :: "r"(addr), "r"(st[4*c]), "r"(st[4*c+1]), "r"(st[4*c+2]), "r"(st[4*c+3])
                : "memory");
        }
    };

    // ---- compute-side ldmatrix geometry (identical to R10)
    const int lr = lid & 7;
    const int q  = lid >> 3;
    const int wco = (wid >> 1) * 32;
    const int wpx = (wid & 1) * 64;
    uint32_t offA[2]; int r7A[2]; const int kselA = q >> 1;
#pragma unroll
    for (int m = 0; m < 2; m++) {
        int r = wco + 16*m + (q & 1)*8 + lr;
        offA[m] = (uint32_t)r * 128u;  r7A[m] = r & 7;
    }
    uint32_t offB[4]; int r7B[4]; const int kselB = q & 1;
#pragma unroll
    for (int j = 0; j < 4; j++) {
        int r = wpx + 16*j + (q >> 1)*8 + lr;
        offB[j] = (uint32_t)r * 128u;  r7B[j] = r & 7;
    }

    float acc[2][8][4];
#pragma unroll
    for (int m = 0; m < 2; m++)
#pragma unroll
        for (int j = 0; j < 8; j++)
#pragma unroll
            for (int v = 0; v < 4; v++) acc[m][j][v] = 0.f;

    // one k16 MMA step s (0..3) on buffer b
    auto compute_s = [&](int b, int s) {
        const uint32_t abase = sb + (uint32_t)b * 16384u;
        const uint32_t bbase = sb + 32768u + (uint32_t)b * 16384u;
        uint32_t Af[2][4];
#pragma unroll
        for (int m = 0; m < 2; m++)
            ldsm4(Af[m], abase + offA[m] + (uint32_t)(((2*s + kselA) ^ r7A[m]) << 4));
#pragma unroll
        for (int j = 0; j < 4; j++) {
            uint32_t Bf[4];
            ldsm4(Bf, bbase + offB[j] + (uint32_t)(((2*s + kselB) ^ r7B[j]) << 4));
#pragma unroll
            for (int m = 0; m < 2; m++) {
                mma16(acc[m][2*j],     Af[m], Bf[0], Bf[1]);
                mma16(acc[m][2*j + 1], Af[m], Bf[2], Bf[3]);
            }
        }
    };

    // ---- pipeline: K-chunks of 64, double buffered, quarters interleaved with MMA steps
    const int nch = K / 64;
#pragma unroll
    for (int qq = 0; qq < 4; qq++) { ldgQ(qq * 16); stsQ(0, qq); }
    __syncthreads();
    for (int i = 0; i < nch; i++) {
        const int b = i & 1, nb = b ^ 1;
        const bool more = (i + 1 < nch);
        const int nk = (i + 1) * 64;
        if (more) ldgQ(nk);
        compute_s(b, 0);
        if (more) { stsQ(nb, 0); ldgQ(nk + 16); }
        compute_s(b, 1);
        if (more) { stsQ(nb, 1); ldgQ(nk + 32); }
        compute_s(b, 2);
        if (more) { stsQ(nb, 2); ldgQ(nk + 48); }
        compute_s(b, 3);
        if (more) stsQ(nb, 3);
        __syncthreads();
    }

    // ---- epilogue
    const int g2 = lid >> 2;
    const int tg = lid & 3;
#pragma unroll
    for (int m = 0; m < 2; m++) {
        int cobase = co0 + wco + 16 * m + g2;
#pragma unroll
        for (int half = 0; half < 2; half++) {
            int co = cobase + 8 * half;
            if (co >= Cout) continue;
            float bsv = bias[co];
#pragma unroll
            for (int j = 0; j < 8; j++) {
                float ox = acc[m][j][2*half]     + bsv;
                float oy = acc[m][j][2*half + 1] + bsv;
                if (ACT) { ox = fmaxf(ox, 0.f); oy = fmaxf(oy, 0.f); }
                int pix = p0 + wpx + 2*tg + 8*j;
                if (OUTM == 1) {
                    int y = pix / WW, x = pix - y * WW;
                    __half* oh = (__half*)out + (long)n * oLane + (long)co * PPIX
                               + (long)(y + 1) * PADW + (x + 2);
                    *(__half2*)oh = __floats2half2_rn(ox, oy);
                } else {
                    long ob;
                    if (OUTM == 2) {
                        int bb = n & 1, tt = n >> 1;
                        ob = ((long)(bb * 5 + tt) * Cout + co) * NPIX + pix;
                    } else {
                        ob = ((long)n * Cout + co) * NPIX + pix;
                    }
                    *(float2*)((float*)out + ob) = make_float2(ox, oy);
                }
            }
        }
    }
}

// ---------------- weight convert kernels ----------------
// permuted: out[co][r*Cin+cin] = w[co][cin*9+r]
__global__ void wperm(const float* __restrict__ w, __half* __restrict__ o, int Cin, int tot)
{
    int id = blockIdx.x * 256 + threadIdx.x;
    if (id >= tot) return;
    int r  = id % 9;
    int t2 = id / 9;
    int cin = t2 % Cin;
    int co  = t2 / Cin;
    o[(long)co * Cin * 9 + r * Cin + cin] = __float2half(w[id]);
}
__global__ void wplain(const float* __restrict__ w, __half* __restrict__ o, int tot)
{
    int id = blockIdx.x * 256 + threadIdx.x;
    if (id >= tot) return;
    o[id] = __float2half(w[id]);
}

// ---------------- stage x slices into padded fp16 ----------------
__global__ void stage_x(const float* __restrict__ inp, int t)
{
    int id = blockIdx.x * blockDim.x + threadIdx.x;   // 4*64*NPIX
    int p  = id % NPIX;
    int r  = id / NPIX;
    int ch = r % 64;
    int n  = r / 64;
    int b  = n & 1;
    int ts = (n < 2) ? t : (4 - t);
    int py = p / WW, px = p - py * WW;
    g_xh[((long)n * 128 + ch) * PPIX + (long)(py + 1) * PADW + px + 2] =
        __float2half(inp[(((long)b * 5 + ts) * 64 + ch) * NPIX + p]);
}

// ---------------- DCN bilinear sampler -> k-contiguous fp16 sampled matrix ----------------
__global__ void dcn_sample(const float* __restrict__ om, __half* __restrict__ sampt)
{
    int id = blockIdx.x * blockDim.x + threadIdx.x;   // 4*8*9*NPIX
    int p  = id % NPIX;
    int r  = id / NPIX;
    int kk = r % 9;  r /= 9;
    int g  = r % 8;
    int n  = r / 8;

    const float* omb = om + (long)n * 216 * NPIX;
    float offy = omb[((g * 9 + kk) * 2 + 0) * NPIX + p];
    float offx = omb[((g * 9 + kk) * 2 + 1) * NPIX + p];
    float m    = sigf(omb[(144 + g * 9 + kk) * NPIX + p]);

    int y  = p / WW;
    int x  = p - y * WW;
    int ky = kk / 3;
    int kx = kk - ky * 3;
    float py = (float)(y + ky - 1) + offy;
    float px = (float)(x + kx - 1) + offx;
    float fy = floorf(py), fx = floorf(px);
    float wy = py - fy,    wx = px - fx;
    int y0 = (int)fy, x0 = (int)fx;
    int y1 = y0 + 1,  x1 = x0 + 1;

    bool vy0 = (y0 >= 0) & (y0 < HH);
    bool vy1 = (y1 >= 0) & (y1 < HH);
    bool vx0 = (x0 >= 0) & (x0 < WW);
    bool vx1 = (x1 >= 0) & (x1 < WW);
    float w00 = (1.f - wy) * (1.f - wx) * (float)(vy0 && vx0);
    float w01 = (1.f - wy) * wx         * (float)(vy0 && vx1);
    float w10 = wy * (1.f - wx)         * (float)(vy1 && vx0);
    float w11 = wy * wx                 * (float)(vy1 && vx1);

    int cy0 = min(max(y0, 0), HH - 1), cy1 = min(max(y1, 0), HH - 1);
    int cx0 = min(max(x0, 0), WW - 1), cx1 = min(max(x1, 0), WW - 1);
    int i00 = (cy0 + 1) * PADW + cx0 + 2, i01 = (cy0 + 1) * PADW + cx1 + 2;
    int i10 = (cy1 + 1) * PADW + cx0 + 2, i11 = (cy1 + 1) * PADW + cx1 + 2;

    const __half* hb = g_xh + ((long)n * 128 + 64 + g * 8) * PPIX;
    __half* op = sampt + ((long)n * 9216 + p) * 576 + (long)(g * 8) * 9 + kk;
#pragma unroll
    for (int cg = 0; cg < 8; cg++) {
        const __half* f = hb + (long)cg * PPIX;
        float v = w00 * __half2float(f[i00]) + w01 * __half2float(f[i01])
                + w10 * __half2float(f[i10]) + w11 * __half2float(f[i11]);
        op[cg * 9] = __float2half(v * m);
    }
}

// ---------------- LSTM pointwise update ----------------
__global__ void lstm_k(const float* __restrict__ cc, float* __restrict__ cbuf, int t)
{
    int id = blockIdx.x * blockDim.x + threadIdx.x;   // 4*64*NPIX
    int p  = id % NPIX;
    int r  = id / NPIX;
    int ch = r % 64;
    int n  = r / 64;

    const float* c4 = cc + (long)n * 256 * NPIX;
    float ci = c4[(      ch) * NPIX + p];
    float cf = c4[( 64 + ch) * NPIX + p];
    float co = c4[(128 + ch) * NPIX + p];
    float cg = c4[(192 + ch) * NPIX + p];

    long hi = ((long)n * 64 + ch) * NPIX + p;
    float c  = cbuf[hi];
    float c2 = sigf(cf) * c + sigf(ci) * tanhf(cg);
    float h2 = sigf(co) * tanhf(c2);
    cbuf[hi] = c2;

    int py = p / WW, px = p - py * WW;
    long pidx = (long)(py + 1) * PADW + px + 2;
    __half hh = __float2half(h2);
    g_xh[((long)n * 128 + 64 + ch) * PPIX + pidx] = hh;
    if (n < 2)
        g_fb[((long)(t * 2 + n) * 128 + ch) * PPIX + pidx] = hh;
    else
        g_fb[((long)((4 - t) * 2 + (n - 2)) * 128 + 64 + ch) * PPIX + pidx] = hh;
}

// ---------------- host orchestration (graph-capturable) ----------------
extern "C" void kernel_launch(void* const* d_in, const int* in_sizes, int n_in,
                              void* d_out, int out_size)
{
    (void)in_sizes; (void)n_in; (void)out_size;
    const float* inp    = (const float*)d_in[0];
    const float* fuse_w = (const float*)d_in[1];
    const float* fuse_b = (const float*)d_in[2];
    const float* om_w   = (const float*)d_in[3];
    const float* om_b   = (const float*)d_in[4];
    const float* dcn_w  = (const float*)d_in[5];
    const float* dcn_b  = (const float*)d_in[6];
    const float* conv_w = (const float*)d_in[7];
    const float* conv_b = (const float*)d_in[8];
    const float* cat_w  = (const float*)d_in[9];
    const float* cat_b  = (const float*)d_in[10];

    __half *xh, *comb, *sampt, *fub, *fb, *wh;
    float *cb, *omb, *ccb;
    cudaGetSymbolAddress((void**)&xh,    g_xh);
    cudaGetSymbolAddress((void**)&cb,    g_c);
    cudaGetSymbolAddress((void**)&comb,  g_comb);
    cudaGetSymbolAddress((void**)&omb,   g_om);
    cudaGetSymbolAddress((void**)&sampt, g_sampt);
    cudaGetSymbolAddress((void**)&fub,   g_fused);
    cudaGetSymbolAddress((void**)&ccb,   g_cc);
    cudaGetSymbolAddress((void**)&fb,    g_fb);
    cudaGetSymbolAddress((void**)&wh,    g_wh);

    cudaFuncSetAttribute(tgemm<0,0,1>, cudaFuncAttributeMaxDynamicSharedMemorySize, SMEM_GEMM_TOTAL);
    cudaFuncSetAttribute(tgemm<0,0,0>, cudaFuncAttributeMaxDynamicSharedMemorySize, SMEM_GEMM_TOTAL);
    cudaFuncSetAttribute(tgemm<1,1,1>, cudaFuncAttributeMaxDynamicSharedMemorySize, SMEM_GEMM_TOTAL);
    cudaFuncSetAttribute(tgemm<0,0,2>, cudaFuncAttributeMaxDynamicSharedMemorySize, SMEM_GEMM_TOTAL);

    // weight converts (fp16, conv weights r-major permuted)
    wperm <<<288, 256>>>(fuse_w, wh + WF_FUSE, 128, 64*128*9);
    wperm <<<486, 256>>>(om_w,   wh + WF_OM,    64, 216*64*9);
    wplain<<<288, 256>>>(dcn_w,  wh + WF_DCN,       128*576);
    wperm <<<1152,256>>>(conv_w, wh + WF_CC,   128, 256*128*9);
    wperm <<<288, 256>>>(cat_w,  wh + WF_CAT,  128, 64*128*9);

    // zero padded buffers (borders must be 0) + cell state
    cudaMemsetAsync(xh,   0, sizeof(__half) * 4  * 128 * PPIX);
    cudaMemsetAsync(comb, 0, sizeof(__half) * 4  * 64  * PPIX);
    cudaMemsetAsync(fub,  0, sizeof(__half) * 4  * 128 * PPIX);
    cudaMemsetAsync(fb,   0, sizeof(__half) * 10 * 128 * PPIX);
    cudaMemsetAsync(cb,   0, sizeof(float)  * 4  * 64  * NPIX);

    for (int t = 0; t < 5; t++) {
        stage_x<<<(4*64*NPIX)/256, 256>>>(inp, t);
        // combined = conv3x3(concat(x,h)) : Cin=128, Cout=64 -> fp16 padded
        tgemm<0,0,1><<<dim3(72, 1, 4), 256, SMEM_GEMM_TOTAL>>>(
            xh, 128L*PPIX, 7, wh + WF_FUSE, fuse_b, comb, 64L*PPIX, 64, 1152);
        // om = conv3x3(combined) : Cin=64, Cout=216 -> f32 flat
        tgemm<0,0,0><<<dim3(72, 2, 4), 256, SMEM_GEMM_TOTAL>>>(
            comb, 64L*PPIX, 6, wh + WF_OM, om_b, omb, 0, 216, 576);
        // DCN sampling -> [n][pix][576] fp16
        dcn_sample<<<(4*8*9*NPIX)/256, 256>>>(omb, sampt);
        // fused = relu(W_dcn @ sampled) : dense K=576 -> fp16 padded
        tgemm<1,1,1><<<dim3(72, 1, 4), 256, SMEM_GEMM_TOTAL>>>(
            sampt, 9216L*576, 0, wh + WF_DCN, dcn_b, fub, 128L*PPIX, 128, 576);
        // cc = conv3x3(fused) : Cin=128, Cout=256 -> f32 flat
        tgemm<0,0,0><<<dim3(72, 2, 4), 256, SMEM_GEMM_TOTAL>>>(
            fub, 128L*PPIX, 7, wh + WF_CC, conv_b, ccb, 0, 256, 1152);
        // LSTM gates + state update (writes h into xh and fb)
        lstm_k<<<(4*64*NPIX)/256, 256>>>(ccb, cb, t);
    }

    // out[b][t] = conv3x3(concat(fwd,bwd)) over all 10 (t,b) lanes
    tgemm<0,0,2><<<dim3(72, 1, 10), 256, SMEM_GEMM_TOTAL>>>(
        fb, 128L*PPIX, 7, wh + WF_CAT, cat_b, d_out, 0, 64, 1152);
}

// round 12
// speedup vs baseline: 4.7136x; 1.5563x over previous
#include <cuda_runtime.h>
#include <cuda_fp16.h>
#include <cstdint>

#define HH 96
#define WW 96
#define NPIX (HH*WW)
#define PADW 100
#define PPIX 9800   // 98 rows x 100 cols, interior (y,x) -> (y+1)*100 + (x+2)

// ---------------- scratch (static device globals; no allocation) ----------------
__device__ __half g_xh[4*128*PPIX];     // ch 0-63: x, ch 64-127: h   (padded fp16)
__device__ float  g_c[4*64*NPIX];       // cell state (f32)
__device__ __half g_comb[4*64*PPIX];    // fuse conv output (padded fp16)
__device__ float  g_om[4*216*NPIX];     // offset/mask conv output (f32)
__device__ __half g_sampt[4*576*NPIX];  // DCN sampled matrix, [n][k][pix] fp16
__device__ __half g_fused[4*128*PPIX];  // DCN output, relu (padded fp16)
__device__ float  g_cc[4*256*NPIX];     // gate conv output (f32)
__device__ __half g_fb[10*128*PPIX];    // cat input: ch0-63 fwd h, ch64-127 bwd h
__device__ __half g_wh[640512];         // all weights fp16 (conv weights r-major)

// weight offsets in g_wh
#define WF_FUSE 0
#define WF_OM   73728
#define WF_DCN  198144
#define WF_CC   271872
#define WF_CAT  566784

__device__ __forceinline__ float sigf(float x){ return 1.f / (1.f + __expf(-x)); }

__device__ __forceinline__ uint32_t s2u(const void* p){
    uint32_t a;
    asm("{ .reg .u64 t; cvta.to.shared.u64 t, %1; cvt.u32.u64 %0, t; }" : "=r"(a) : "l"(p));
    return a;
}
__device__ __forceinline__ void ldsm4(uint32_t r[4], uint32_t addr){
    asm volatile("ldmatrix.sync.aligned.m8n8.x4.shared.b16 {%0,%1,%2,%3}, [%4];"
        : "=r"(r[0]), "=r"(r[1]), "=r"(r[2]), "=r"(r[3]) : "r"(addr));
}
__device__ __forceinline__ void mma16(float c[4], const uint32_t a[4], uint32_t b0, uint32_t b1){
    asm volatile(
        "mma.sync.aligned.m16n8k16.row.col.f32.f16.f16.f32 "
        "{%0,%1,%2,%3}, {%4,%5,%6,%7}, {%8,%9}, {%0,%1,%2,%3};"
        : "+f"(c[0]), "+f"(c[1]), "+f"(c[2]), "+f"(c[3])
        : "r"(a[0]), "r"(a[1]), "r"(a[2]), "r"(a[3]), "r"(b0), "r"(b1));
}

static constexpr int SMEM_GEMM_TOTAL = 65536;

// ================= f16 HMMA implicit-GEMM =================
// D[n][co][pix] = sum_k W[co][k] * Im[pix][k]  (+bias, opt relu)
// MT: co tile (128 or 64). Warp grid 4co x 2px (MT=128) or 2co x 4px (MT=64).
// MODE 0: conv3x3 over padded fp16 buffer, k-order r-major: k = r*Cin + cin
//         (weights pre-permuted). Cin = 1<<cinlog.
// MODE 1: Im[pix][k] = in0[n][k][pix]  ([k][pix] fp16, coalesced across threads)
// OUTM 0: f32 flat [n][Cout][NPIX] ; 1: fp16 padded [n][co][PPIX] (oLane=ch*PPIX)
// OUTM 2: f32 flat with n=t*2+b -> [(b*5+t)][co][NPIX]
template<int MT, int MODE, int ACT, int OUTM>
__global__ __launch_bounds__(256, 2) void tgemm(
    const __half* __restrict__ in0, long s0, int cinlog,
    const __half* __restrict__ wh, const float* __restrict__ bias,
    void* __restrict__ out, long oLane, int Cout, int K)
{
    constexpr int NB = (MT == 128) ? 4 : 2;   // B n16-tiles per warp
    extern __shared__ char dsm[];
    const uint32_t sb = s2u(dsm);
    const int tid = threadIdx.x;
    const int wid = tid >> 5;
    const int lid = tid & 31;
    const int n   = blockIdx.z;
    const int p0  = blockIdx.x * 128;
    const int co0 = blockIdx.y * MT;

    // ---- staging role: tid<128 stages B row (pixel), tid>=128 stages A row (cout)
    const bool isB = (tid < 128);
    const int  srow = isB ? tid : (tid - 128);
    const bool act  = isB || (srow < MT);     // A stagers beyond MT idle
    const int  spg = p0 + srow;
    const int  spy = spg / WW;
    const int  spx = spg - spy * WW;
    const int  sco = co0 + srow;
    const bool wok = (sco < Cout) && (srow < MT);
    // B mode0: padded lane base incl. pixel ; mode1: [k][pix] base at this pixel
    const unsigned short* laneB0 =
        (const unsigned short*)(in0 + (long)n * s0) + (long)(spy + 1) * PADW + (spx + 2);
    const unsigned short* laneB1 =
        (const unsigned short*)(in0 + (long)n * s0) + spg;
    const uint4* wrow = (const uint4*)(wh + (long)sco * K);
    const uint32_t stsRole = sb + (isB ? 32768u : 0u) + (uint32_t)srow * 128u;
    const int  sr7 = srow & 7;

    unsigned hv[16];   // B raw u16 quarter
    unsigned st[8];    // staged u32 quarter (A vector loads)

    // load one quarter (16 k's): kk0 = chunk*64 + q*16
    auto ldgQ = [&](int kk0) {
        if (isB) {
            if (MODE == 0) {
                const int r    = kk0 >> cinlog;
                const int cinb = kk0 & ((1 << cinlog) - 1);
                const int dy   = r / 3;
                const int pdv  = (dy - 1) * PADW + (r - dy * 3 - 1);
                const unsigned short* bt = laneB0 + (long)cinb * PPIX + pdv;
#pragma unroll
                for (int j = 0; j < 16; j++)
                    hv[j] = __ldg(bt + (long)j * PPIX);
            } else {
                const unsigned short* bt = laneB1 + (long)kk0 * NPIX;
#pragma unroll
                for (int j = 0; j < 16; j++)
                    hv[j] = __ldg(bt + (long)j * NPIX);
            }
        } else if (act) {
            if (wok) {
                const uint4* wp = wrow + (kk0 >> 3);
                uint4 q0 = __ldg(wp);
                uint4 q1 = __ldg(wp + 1);
                st[0]=q0.x; st[1]=q0.y; st[2]=q0.z; st[3]=q0.w;
                st[4]=q1.x; st[5]=q1.y; st[6]=q1.z; st[7]=q1.w;
            } else {
#pragma unroll
                for (int j = 0; j < 8; j++) st[j] = 0u;
            }
        }
    };
    // store quarter q of buffer b (16 k -> groups cg=2q, 2q+1)
    auto stsQ = [&](int b, int q) {
        if (!act) return;
        if (isB) {
#pragma unroll
            for (int j = 0; j < 8; j++)
                st[j] = hv[2*j] | (hv[2*j + 1] << 16);
        }
        uint32_t base = stsRole + (uint32_t)b * 16384u;
#pragma unroll
        for (int c = 0; c < 2; c++) {
            int cg = 2*q + c;
            uint32_t addr = base + (uint32_t)((cg ^ sr7) << 4);
            asm volatile("st.shared.v4.b32 [%0], {%1, %2, %3, %4};"
                :: "r"(addr), "r"(st[4*c]), "r"(st[4*c+1]), "r"(st[4*c+2]), "r"(st[4*c+3])
                : "memory");
        }
    };

    // ---- compute-side ldmatrix geometry
    const int lr = lid & 7;
    const int q  = lid >> 3;
    const int wco = (MT == 128) ? (wid >> 1) * 32 : (wid >> 2) * 32;
    const int wpx = (MT == 128) ? (wid & 1) * 64  : (wid & 3) * 32;
    uint32_t offA[2]; int r7A[2]; const int kselA = q >> 1;
#pragma unroll
    for (int m = 0; m < 2; m++) {
        int r = wco + 16*m + (q & 1)*8 + lr;
        offA[m] = (uint32_t)r * 128u;  r7A[m] = r & 7;
    }
    uint32_t offB[NB]; int r7B[NB]; const int kselB = q & 1;
#pragma unroll
    for (int j = 0; j < NB; j++) {
        int r = wpx + 16*j + (q >> 1)*8 + lr;
        offB[j] = (uint32_t)r * 128u;  r7B[j] = r & 7;
    }

    float acc[2][2*NB][4];
#pragma unroll
    for (int m = 0; m < 2; m++)
#pragma unroll
        for (int j = 0; j < 2*NB; j++)
#pragma unroll
            for (int v = 0; v < 4; v++) acc[m][j][v] = 0.f;

    // one k16 MMA step s (0..3) on buffer b
    auto compute_s = [&](int b, int s) {
        const uint32_t abase = sb + (uint32_t)b * 16384u;
        const uint32_t bbase = sb + 32768u + (uint32_t)b * 16384u;
        uint32_t Af[2][4];
#pragma unroll
        for (int m = 0; m < 2; m++)
            ldsm4(Af[m], abase + offA[m] + (uint32_t)(((2*s + kselA) ^ r7A[m]) << 4));
#pragma unroll
        for (int j = 0; j < NB; j++) {
            uint32_t Bf[4];
            ldsm4(Bf, bbase + offB[j] + (uint32_t)(((2*s + kselB) ^ r7B[j]) << 4));
#pragma unroll
            for (int m = 0; m < 2; m++) {
                mma16(acc[m][2*j],     Af[m], Bf[0], Bf[1]);
                mma16(acc[m][2*j + 1], Af[m], Bf[2], Bf[3]);
            }
        }
    };

    // ---- pipeline: K-chunks of 64, double buffered, quarters interleaved with MMA steps
    const int nch = K / 64;
#pragma unroll
    for (int qq = 0; qq < 4; qq++) { ldgQ(qq * 16); stsQ(0, qq); }
    __syncthreads();
    for (int i = 0; i < nch; i++) {
        const int b = i & 1, nb = b ^ 1;
        const bool more = (i + 1 < nch);
        const int nk = (i + 1) * 64;
        if (more) ldgQ(nk);
        compute_s(b, 0);
        if (more) { stsQ(nb, 0); ldgQ(nk + 16); }
        compute_s(b, 1);
        if (more) { stsQ(nb, 1); ldgQ(nk + 32); }
        compute_s(b, 2);
        if (more) { stsQ(nb, 2); ldgQ(nk + 48); }
        compute_s(b, 3);
        if (more) stsQ(nb, 3);
        __syncthreads();
    }

    // ---- epilogue
    const int g2 = lid >> 2;
    const int tg = lid & 3;
#pragma unroll
    for (int m = 0; m < 2; m++) {
        int cobase = co0 + wco + 16 * m + g2;
#pragma unroll
        for (int half = 0; half < 2; half++) {
            int co = cobase + 8 * half;
            if (co >= Cout) continue;
            float bsv = bias[co];
#pragma unroll
            for (int j = 0; j < 2*NB; j++) {
                float ox = acc[m][j][2*half]     + bsv;
                float oy = acc[m][j][2*half + 1] + bsv;
                if (ACT) { ox = fmaxf(ox, 0.f); oy = fmaxf(oy, 0.f); }
                int pix = p0 + wpx + 2*tg + 8*j;
                if (OUTM == 1) {
                    int y = pix / WW, x = pix - y * WW;
                    __half* oh = (__half*)out + (long)n * oLane + (long)co * PPIX
                               + (long)(y + 1) * PADW + (x + 2);
                    *(__half2*)oh = __floats2half2_rn(ox, oy);
                } else {
                    long ob;
                    if (OUTM == 2) {
                        int bb = n & 1, tt = n >> 1;
                        ob = ((long)(bb * 5 + tt) * Cout + co) * NPIX + pix;
                    } else {
                        ob = ((long)n * Cout + co) * NPIX + pix;
                    }
                    *(float2*)((float*)out + ob) = make_float2(ox, oy);
                }
            }
        }
    }
}

// ---------------- weight convert kernels ----------------
// permuted: out[co][r*Cin+cin] = w[co][cin*9+r]
__global__ void wperm(const float* __restrict__ w, __half* __restrict__ o, int Cin, int tot)
{
    int id = blockIdx.x * 256 + threadIdx.x;
    if (id >= tot) return;
    int r  = id % 9;
    int t2 = id / 9;
    int cin = t2 % Cin;
    int co  = t2 / Cin;
    o[(long)co * Cin * 9 + r * Cin + cin] = __float2half(w[id]);
}
__global__ void wplain(const float* __restrict__ w, __half* __restrict__ o, int tot)
{
    int id = blockIdx.x * 256 + threadIdx.x;
    if (id >= tot) return;
    o[id] = __float2half(w[id]);
}

// ---------------- stage x slices into padded fp16 ----------------
__global__ void stage_x(const float* __restrict__ inp, int t)
{
    int id = blockIdx.x * blockDim.x + threadIdx.x;   // 4*64*NPIX
    int p  = id % NPIX;
    int r  = id / NPIX;
    int ch = r % 64;
    int n  = r / 64;
    int b  = n & 1;
    int ts = (n < 2) ? t : (4 - t);
    int py = p / WW, px = p - py * WW;
    g_xh[((long)n * 128 + ch) * PPIX + (long)(py + 1) * PADW + px + 2] =
        __float2half(inp[(((long)b * 5 + ts) * 64 + ch) * NPIX + p]);
}

// ---------------- DCN bilinear sampler -> [n][k][pix] fp16 (coalesced stores) ----------------
__global__ void dcn_sample(const float* __restrict__ om, __half* __restrict__ sampt)
{
    int id = blockIdx.x * blockDim.x + threadIdx.x;   // 4*8*9*NPIX
    int p  = id % NPIX;
    int r  = id / NPIX;
    int kk = r % 9;  r /= 9;
    int g  = r % 8;
    int n  = r / 8;

    const float* omb = om + (long)n * 216 * NPIX;
    float offy = omb[((g * 9 + kk) * 2 + 0) * NPIX + p];
    float offx = omb[((g * 9 + kk) * 2 + 1) * NPIX + p];
    float m    = sigf(omb[(144 + g * 9 + kk) * NPIX + p]);

    int y  = p / WW;
    int x  = p - y * WW;
    int ky = kk / 3;
    int kx = kk - ky * 3;
    float py = (float)(y + ky - 1) + offy;
    float px = (float)(x + kx - 1) + offx;
    float fy = floorf(py), fx = floorf(px);
    float wy = py - fy,    wx = px - fx;
    int y0 = (int)fy, x0 = (int)fx;
    int y1 = y0 + 1,  x1 = x0 + 1;

    bool vy0 = (y0 >= 0) & (y0 < HH);
    bool vy1 = (y1 >= 0) & (y1 < HH);
    bool vx0 = (x0 >= 0) & (x0 < WW);
    bool vx1 = (x1 >= 0) & (x1 < WW);
    float w00 = (1.f - wy) * (1.f - wx) * (float)(vy0 && vx0);
    float w01 = (1.f - wy) * wx         * (float)(vy0 && vx1);
    float w10 = wy * (1.f - wx)         * (float)(vy1 && vx0);
    float w11 = wy * wx                 * (float)(vy1 && vx1);

    int cy0 = min(max(y0, 0), HH - 1), cy1 = min(max(y1, 0), HH - 1);
    int cx0 = min(max(x0, 0), WW - 1), cx1 = min(max(x1, 0), WW - 1);
    int i00 = (cy0 + 1) * PADW + cx0 + 2, i01 = (cy0 + 1) * PADW + cx1 + 2;
    int i10 = (cy1 + 1) * PADW + cx0 + 2, i11 = (cy1 + 1) * PADW + cx1 + 2;

    const __half* hb = g_xh + ((long)n * 128 + 64 + g * 8) * PPIX;
    // k = (g*8+cg)*9 + kk ; layout [n][k][pix] -> adjacent threads (adjacent p) coalesce
    __half* op = sampt + ((long)n * 576 + (long)(g * 8) * 9 + kk) * NPIX + p;
#pragma unroll
    for (int cg = 0; cg < 8; cg++) {
        const __half* f = hb + (long)cg * PPIX;
        float v = w00 * __half2float(f[i00]) + w01 * __half2float(f[i01])
                + w10 * __half2float(f[i10]) + w11 * __half2float(f[i11]);
        op[(long)cg * 9 * NPIX] = __float2half(v * m);
    }
}

// ---------------- LSTM pointwise update ----------------
__global__ void lstm_k(const float* __restrict__ cc, float* __restrict__ cbuf, int t)
{
    int id = blockIdx.x * blockDim.x + threadIdx.x;   // 4*64*NPIX
    int p  = id % NPIX;
    int r  = id / NPIX;
    int ch = r % 64;
    int n  = r / 64;

    const float* c4 = cc + (long)n * 256 * NPIX;
    float ci = c4[(      ch) * NPIX + p];
    float cf = c4[( 64 + ch) * NPIX + p];
    float co = c4[(128 + ch) * NPIX + p];
    float cg = c4[(192 + ch) * NPIX + p];

    long hi = ((long)n * 64 + ch) * NPIX + p;
    float c  = cbuf[hi];
    float c2 = sigf(cf) * c + sigf(ci) * tanhf(cg);
    float h2 = sigf(co) * tanhf(c2);
    cbuf[hi] = c2;

    int py = p / WW, px = p - py * WW;
    long pidx = (long)(py + 1) * PADW + px + 2;
    __half hh = __float2half(h2);
    g_xh[((long)n * 128 + 64 + ch) * PPIX + pidx] = hh;
    if (n < 2)
        g_fb[((long)(t * 2 + n) * 128 + ch) * PPIX + pidx] = hh;
    else
        g_fb[((long)((4 - t) * 2 + (n - 2)) * 128 + 64 + ch) * PPIX + pidx] = hh;
}

// ---------------- host orchestration (graph-capturable) ----------------
extern "C" void kernel_launch(void* const* d_in, const int* in_sizes, int n_in,
                              void* d_out, int out_size)
{
    (void)in_sizes; (void)n_in; (void)out_size;
    const float* inp    = (const float*)d_in[0];
    const float* fuse_w = (const float*)d_in[1];
    const float* fuse_b = (const float*)d_in[2];
    const float* om_w   = (const float*)d_in[3];
    const float* om_b   = (const float*)d_in[4];
    const float* dcn_w  = (const float*)d_in[5];
    const float* dcn_b  = (const float*)d_in[6];
    const float* conv_w = (const float*)d_in[7];
    const float* conv_b = (const float*)d_in[8];
    const float* cat_w  = (const float*)d_in[9];
    const float* cat_b  = (const float*)d_in[10];

    __half *xh, *comb, *sampt, *fub, *fb, *wh;
    float *cb, *omb, *ccb;
    cudaGetSymbolAddress((void**)&xh,    g_xh);
    cudaGetSymbolAddress((void**)&cb,    g_c);
    cudaGetSymbolAddress((void**)&comb,  g_comb);
    cudaGetSymbolAddress((void**)&omb,   g_om);
    cudaGetSymbolAddress((void**)&sampt, g_sampt);
    cudaGetSymbolAddress((void**)&fub,   g_fused);
    cudaGetSymbolAddress((void**)&ccb,   g_cc);
    cudaGetSymbolAddress((void**)&fb,    g_fb);
    cudaGetSymbolAddress((void**)&wh,    g_wh);

    cudaFuncSetAttribute(tgemm<64,0,0,1>,  cudaFuncAttributeMaxDynamicSharedMemorySize, SMEM_GEMM_TOTAL);
    cudaFuncSetAttribute(tgemm<128,0,0,0>, cudaFuncAttributeMaxDynamicSharedMemorySize, SMEM_GEMM_TOTAL);
    cudaFuncSetAttribute(tgemm<128,1,1,1>, cudaFuncAttributeMaxDynamicSharedMemorySize, SMEM_GEMM_TOTAL);
    cudaFuncSetAttribute(tgemm<64,0,0,2>,  cudaFuncAttributeMaxDynamicSharedMemorySize, SMEM_GEMM_TOTAL);

    // weight converts (fp16, conv weights r-major permuted)
    wperm <<<288, 256>>>(fuse_w, wh + WF_FUSE, 128, 64*128*9);
    wperm <<<486, 256>>>(om_w,   wh + WF_OM,    64, 216*64*9);
    wplain<<<288, 256>>>(dcn_w,  wh + WF_DCN,       128*576);
    wperm <<<1152,256>>>(conv_w, wh + WF_CC,   128, 256*128*9);
    wperm <<<288, 256>>>(cat_w,  wh + WF_CAT,  128, 64*128*9);

    // zero padded buffers (borders must be 0) + cell state
    cudaMemsetAsync(xh,   0, sizeof(__half) * 4  * 128 * PPIX);
    cudaMemsetAsync(comb, 0, sizeof(__half) * 4  * 64  * PPIX);
    cudaMemsetAsync(fub,  0, sizeof(__half) * 4  * 128 * PPIX);
    cudaMemsetAsync(fb,   0, sizeof(__half) * 10 * 128 * PPIX);
    cudaMemsetAsync(cb,   0, sizeof(float)  * 4  * 64  * NPIX);

    for (int t = 0; t < 5; t++) {
        stage_x<<<(4*64*NPIX)/256, 256>>>(inp, t);
        // combined = conv3x3(concat(x,h)) : Cin=128, Cout=64 -> fp16 padded (M64 tile)
        tgemm<64,0,0,1><<<dim3(72, 1, 4), 256, SMEM_GEMM_TOTAL>>>(
            xh, 128L*PPIX, 7, wh + WF_FUSE, fuse_b, comb, 64L*PPIX, 64, 1152);
        // om = conv3x3(combined) : Cin=64, Cout=216 -> f32 flat
        tgemm<128,0,0,0><<<dim3(72, 2, 4), 256, SMEM_GEMM_TOTAL>>>(
            comb, 64L*PPIX, 6, wh + WF_OM, om_b, omb, 0, 216, 576);
        // DCN sampling -> [n][576][NPIX] fp16
        dcn_sample<<<(4*8*9*NPIX)/256, 256>>>(omb, sampt);
        // fused = relu(W_dcn @ sampled) : dense K=576 -> fp16 padded
        tgemm<128,1,1,1><<<dim3(72, 1, 4), 256, SMEM_GEMM_TOTAL>>>(
            sampt, 576L*NPIX, 0, wh + WF_DCN, dcn_b, fub, 128L*PPIX, 128, 576);
        // cc = conv3x3(fused) : Cin=128, Cout=256 -> f32 flat
        tgemm<128,0,0,0><<<dim3(72, 2, 4), 256, SMEM_GEMM_TOTAL>>>(
            fub, 128L*PPIX, 7, wh + WF_CC, conv_b, ccb, 0, 256, 1152);
        // LSTM gates + state update (writes h into xh and fb)
        lstm_k<<<(4*64*NPIX)/256, 256>>>(ccb, cb, t);
    }

    // out[b][t] = conv3x3(concat(fwd,bwd)) over all 10 (t,b) lanes (M64 tile)
    tgemm<64,0,0,2><<<dim3(72, 1, 10), 256, SMEM_GEMM_TOTAL>>>(
        fb, 128L*PPIX, 7, wh + WF_CAT, cat_b, d_out, 0, 64, 1152);
}